// round 3
// baseline (speedup 1.0000x reference)
#include <cuda_runtime.h>
#include <cuda_bf16.h>

// AllReduce(sum over tp=8) + residual add + RMSNorm, fused.
// R3: persistent kernel (592 resident CTAs = 148 SMs x 4, single wave, no
// wave-tail quantization), one __syncthreads per token (redundant final
// reduce per thread), weight cached in registers across tokens.

constexpr int TOKENS = 4096;
constexpr int HIDDEN = 4096;
constexpr int TP     = 8;
constexpr int H4     = HIDDEN / 4;        // 1024 float4 per row
constexpr int NTHREADS = 256;
constexpr int NWARPS  = NTHREADS / 32;
constexpr int CHUNKS = H4 / NTHREADS;     // 4 float4 per thread
constexpr int GRID   = 148 * 4;           // resident on all SMs
constexpr float EPS = 1e-6f;

__global__ __launch_bounds__(NTHREADS, 4) void allreduce_rmsnorm_kernel(
    const float4* __restrict__ input,     // [TP, TOKENS, H4]
    const float4* __restrict__ residual,  // [TOKENS, H4]
    const float4* __restrict__ weight,    // [H4]
    float4* __restrict__ out_norm,        // [TOKENS, H4]
    float4* __restrict__ out_hidden)      // [TOKENS, H4]
{
    const int tid  = threadIdx.x;
    const int lane = tid & 31;
    const int wid  = tid >> 5;

    const size_t tp_stride = (size_t)TOKENS * H4;

    // Weight: load once, reuse for every token this CTA processes.
    float4 wv[CHUNKS];
    #pragma unroll
    for (int c = 0; c < CHUNKS; c++)
        wv[c] = __ldg(&weight[tid + c * NTHREADS]);

    __shared__ float warp_ss[2][NWARPS];

    int parity = 0;
    for (int token = blockIdx.x; token < TOKENS; token += GRID, parity ^= 1) {
        const size_t row_off = (size_t)token * H4;
        const float4* __restrict__ res_row = residual + row_off;
        const float4* __restrict__ in_row  = input + row_off;

        float4 acc[CHUNKS];
        float ss = 0.0f;

        // Fused TP-sum + residual add; 36 independent streaming loads/thread.
        #pragma unroll
        for (int c = 0; c < CHUNKS; c++) {
            const int idx = tid + c * NTHREADS;
            float4 a = __ldcs(&res_row[idx]);
            #pragma unroll
            for (int t = 0; t < TP; t++) {
                float4 v = __ldcs(&in_row[(size_t)t * tp_stride + idx]);
                a.x += v.x; a.y += v.y; a.z += v.z; a.w += v.w;
            }
            acc[c] = a;
            ss = fmaf(a.x, a.x, ss);
            ss = fmaf(a.y, a.y, ss);
            ss = fmaf(a.z, a.z, ss);
            ss = fmaf(a.w, a.w, ss);
        }

        // New-residual store is independent of rstd: issue before the barrier
        // so store traffic overlaps the reduce window.
        #pragma unroll
        for (int c = 0; c < CHUNKS; c++)
            __stcs(&out_hidden[row_off + tid + c * NTHREADS], acc[c]);

        // Warp reduce, then single barrier; every thread finishes the
        // reduction redundantly (8 smem broadcast reads + rsqrt).
        #pragma unroll
        for (int off = 16; off > 0; off >>= 1)
            ss += __shfl_xor_sync(0xFFFFFFFFu, ss, off);
        if (lane == 0) warp_ss[parity][wid] = ss;
        __syncthreads();

        float tot = 0.0f;
        #pragma unroll
        for (int w = 0; w < NWARPS; w++)
            tot += warp_ss[parity][w];
        const float rstd = rsqrtf(tot * (1.0f / (float)HIDDEN) + EPS);

        // Normalized output.
        #pragma unroll
        for (int c = 0; c < CHUNKS; c++) {
            const float4 a = acc[c];
            const float4 w = wv[c];
            float4 n;
            n.x = a.x * rstd * w.x;
            n.y = a.y * rstd * w.y;
            n.z = a.z * rstd * w.z;
            n.w = a.w * rstd * w.w;
            __stcs(&out_norm[row_off + tid + c * NTHREADS], n);
        }
    }
}

extern "C" void kernel_launch(void* const* d_in, const int* in_sizes, int n_in,
                              void* d_out, int out_size)
{
    const float4* input    = (const float4*)d_in[0];
    const float4* residual = (const float4*)d_in[1];
    const float4* weight   = (const float4*)d_in[2];

    float4* out_norm   = (float4*)d_out;
    float4* out_hidden = (float4*)((float*)d_out + (size_t)TOKENS * HIDDEN);

    allreduce_rmsnorm_kernel<<<GRID, NTHREADS>>>(
        input, residual, weight, out_norm, out_hidden);
}

// round 4
// speedup vs baseline: 1.0472x; 1.0472x over previous
#include <cuda_runtime.h>
#include <cuda_bf16.h>

// AllReduce(sum over tp=8) + residual add + RMSNorm, fused single pass.
// R4: back to one-CTA-per-token (R2 structure, the best so far), but with
// 512 threads / CHUNKS=2 to cut per-thread register state (acc[2] instead of
// acc[4]) -> lower regs -> more resident warps -> more outstanding loads.
// Evidence: DRAM% tracks occupancy across R1/R3 (60%->84%, 48%->81.6%).

constexpr int TOKENS = 4096;
constexpr int HIDDEN = 4096;
constexpr int TP     = 8;
constexpr int H4     = HIDDEN / 4;        // 1024 float4 per row
constexpr int NTHREADS = 512;
constexpr int NWARPS  = NTHREADS / 32;    // 16
constexpr int CHUNKS = H4 / NTHREADS;     // 2 float4 per thread
constexpr float EPS = 1e-6f;

__global__ __launch_bounds__(NTHREADS) void allreduce_rmsnorm_kernel(
    const float4* __restrict__ input,     // [TP, TOKENS, H4]
    const float4* __restrict__ residual,  // [TOKENS, H4]
    const float4* __restrict__ weight,    // [H4]
    float4* __restrict__ out_norm,        // [TOKENS, H4]
    float4* __restrict__ out_hidden)      // [TOKENS, H4]
{
    const int token = blockIdx.x;
    const int tid   = threadIdx.x;
    const int lane  = tid & 31;
    const int wid   = tid >> 5;

    const size_t row_off   = (size_t)token * H4;
    const size_t tp_stride = (size_t)TOKENS * H4;

    const float4* __restrict__ res_row = residual + row_off;
    const float4* __restrict__ in_row  = input + row_off;

    float4 acc[CHUNKS];
    float ss = 0.0f;

    // Fused TP-sum + residual add; 9 independent streaming loads per chunk.
    #pragma unroll
    for (int c = 0; c < CHUNKS; c++) {
        const int idx = tid + c * NTHREADS;
        float4 a = __ldcs(&res_row[idx]);
        #pragma unroll
        for (int t = 0; t < TP; t++) {
            float4 v = __ldcs(&in_row[(size_t)t * tp_stride + idx]);
            a.x += v.x; a.y += v.y; a.z += v.z; a.w += v.w;
        }
        acc[c] = a;
        ss = fmaf(a.x, a.x, ss);
        ss = fmaf(a.y, a.y, ss);
        ss = fmaf(a.z, a.z, ss);
        ss = fmaf(a.w, a.w, ss);
    }

    // Residual-stream output does not depend on rstd: store before the
    // barrier so DRAM stays busy through the reduce window.
    #pragma unroll
    for (int c = 0; c < CHUNKS; c++)
        __stcs(&out_hidden[row_off + tid + c * NTHREADS], acc[c]);

    // Warp reduce -> smem -> single barrier -> redundant per-thread finish.
    #pragma unroll
    for (int off = 16; off > 0; off >>= 1)
        ss += __shfl_xor_sync(0xFFFFFFFFu, ss, off);

    __shared__ float warp_ss[NWARPS];
    if (lane == 0) warp_ss[wid] = ss;
    __syncthreads();

    float tot = 0.0f;
    #pragma unroll
    for (int w = 0; w < NWARPS; w++)
        tot += warp_ss[w];
    const float rstd = rsqrtf(tot * (1.0f / (float)HIDDEN) + EPS);

    // Normalized output; weight is 16KB and shared by all CTAs -> L2-cached.
    #pragma unroll
    for (int c = 0; c < CHUNKS; c++) {
        const int idx = tid + c * NTHREADS;
        const float4 a = acc[c];
        const float4 w = __ldg(&weight[idx]);
        float4 n;
        n.x = a.x * rstd * w.x;
        n.y = a.y * rstd * w.y;
        n.z = a.z * rstd * w.z;
        n.w = a.w * rstd * w.w;
        __stcs(&out_norm[row_off + idx], n);
    }
}

extern "C" void kernel_launch(void* const* d_in, const int* in_sizes, int n_in,
                              void* d_out, int out_size)
{
    const float4* input    = (const float4*)d_in[0];
    const float4* residual = (const float4*)d_in[1];
    const float4* weight   = (const float4*)d_in[2];

    float4* out_norm   = (float4*)d_out;
    float4* out_hidden = (float4*)((float*)d_out + (size_t)TOKENS * HIDDEN);

    allreduce_rmsnorm_kernel<<<TOKENS, NTHREADS>>>(
        input, residual, weight, out_norm, out_hidden);
}

// round 5
// speedup vs baseline: 1.0513x; 1.0039x over previous
#include <cuda_runtime.h>
#include <cuda_bf16.h>

// AllReduce(sum over tp=8) + residual add + RMSNorm, fused single pass.
// R5: R4 structure (512 thr, CHUNKS=2, one CTA per token) + register clamp
// to 32 via __launch_bounds__(512, 4) -> 4 CTAs/SM = 64 warps = full
// occupancy. Trades per-thread load batch depth (~9 -> ~5 in flight) for
// +33% resident warps; occ->DRAM% correlation (48->81.6, 60->84.0,
// 75->85.8) says warps win.

constexpr int TOKENS = 4096;
constexpr int HIDDEN = 4096;
constexpr int TP     = 8;
constexpr int H4     = HIDDEN / 4;        // 1024 float4 per row
constexpr int NTHREADS = 512;
constexpr int NWARPS  = NTHREADS / 32;    // 16
constexpr int CHUNKS = H4 / NTHREADS;     // 2 float4 per thread
constexpr float EPS = 1e-6f;

__global__ __launch_bounds__(NTHREADS, 4) void allreduce_rmsnorm_kernel(
    const float4* __restrict__ input,     // [TP, TOKENS, H4]
    const float4* __restrict__ residual,  // [TOKENS, H4]
    const float4* __restrict__ weight,    // [H4]
    float4* __restrict__ out_norm,        // [TOKENS, H4]
    float4* __restrict__ out_hidden)      // [TOKENS, H4]
{
    const int token = blockIdx.x;
    const int tid   = threadIdx.x;
    const int lane  = tid & 31;
    const int wid   = tid >> 5;

    const size_t row_off   = (size_t)token * H4;
    const size_t tp_stride = (size_t)TOKENS * H4;

    const float4* __restrict__ res_row = residual + row_off;
    const float4* __restrict__ in_row  = input + row_off;

    float4 acc[CHUNKS];
    float ss = 0.0f;

    // Fused TP-sum + residual add; streaming loads (zero reuse).
    #pragma unroll
    for (int c = 0; c < CHUNKS; c++) {
        const int idx = tid + c * NTHREADS;
        float4 a = __ldcs(&res_row[idx]);
        #pragma unroll
        for (int t = 0; t < TP; t++) {
            float4 v = __ldcs(&in_row[(size_t)t * tp_stride + idx]);
            a.x += v.x; a.y += v.y; a.z += v.z; a.w += v.w;
        }
        acc[c] = a;
        ss = fmaf(a.x, a.x, ss);
        ss = fmaf(a.y, a.y, ss);
        ss = fmaf(a.z, a.z, ss);
        ss = fmaf(a.w, a.w, ss);
    }

    // Residual-stream output does not depend on rstd: store before the
    // barrier so DRAM stays busy through the reduce window.
    #pragma unroll
    for (int c = 0; c < CHUNKS; c++)
        __stcs(&out_hidden[row_off + tid + c * NTHREADS], acc[c]);

    // Warp reduce -> smem -> single barrier -> redundant per-thread finish.
    #pragma unroll
    for (int off = 16; off > 0; off >>= 1)
        ss += __shfl_xor_sync(0xFFFFFFFFu, ss, off);

    __shared__ float warp_ss[NWARPS];
    if (lane == 0) warp_ss[wid] = ss;
    __syncthreads();

    float tot = 0.0f;
    #pragma unroll
    for (int w = 0; w < NWARPS; w++)
        tot += warp_ss[w];
    const float rstd = rsqrtf(tot * (1.0f / (float)HIDDEN) + EPS);

    // Normalized output; weight is 16KB and shared by all CTAs -> L2-cached.
    #pragma unroll
    for (int c = 0; c < CHUNKS; c++) {
        const int idx = tid + c * NTHREADS;
        const float4 a = acc[c];
        const float4 w = __ldg(&weight[idx]);
        float4 n;
        n.x = a.x * rstd * w.x;
        n.y = a.y * rstd * w.y;
        n.z = a.z * rstd * w.z;
        n.w = a.w * rstd * w.w;
        __stcs(&out_norm[row_off + idx], n);
    }
}

extern "C" void kernel_launch(void* const* d_in, const int* in_sizes, int n_in,
                              void* d_out, int out_size)
{
    const float4* input    = (const float4*)d_in[0];
    const float4* residual = (const float4*)d_in[1];
    const float4* weight   = (const float4*)d_in[2];

    float4* out_norm   = (float4*)d_out;
    float4* out_hidden = (float4*)((float*)d_out + (size_t)TOKENS * HIDDEN);

    allreduce_rmsnorm_kernel<<<TOKENS, NTHREADS>>>(
        input, residual, weight, out_norm, out_hidden);
}